// round 1
// baseline (speedup 1.0000x reference)
#include <cuda_runtime.h>

#define BATCH 64
#define TT    200
#define NUM_C 2000
#define DIM   128
#define MM    50
#define MP    56          // M padded; rows 50..55 have w=0 (inert)
#define NX    4000        // distinct x = skill + 2000*answer

// ---------------- scratch (device globals; no allocation allowed) ----------
__device__ __align__(16) float g_w[NUM_C * MP];       // softmax(k·Mk^T) per skill id
__device__ __align__(16) float g_ea[NX * 256];        // [x][0:128]=e, [128:256]=a
__device__ __align__(16) float g_kf[NUM_C * DIM];     // k-part of f GEMM + f_b folded
__device__ __align__(16) float g_reads[BATCH * TT * DIM];
__device__ __align__(16) float g_eaWt[DIM * 256];     // [k][c]: c<128 -> e_W[c][k], else a_W
__device__ __align__(16) float g_fWat[DIM * DIM];     // [k][i] = f_W[i*256 + k]       (reads part)
__device__ __align__(16) float g_fWbt[DIM * DIM];     // [k][i] = f_W[i*256 + 128 + k] (k part)

__device__ __forceinline__ float sigmoidf_(float x) { return 1.f / (1.f + __expf(-x)); }

// ---------------- weight transposes (run once per launch, cheap) ----------
__global__ void k_setup(const float* __restrict__ eW, const float* __restrict__ aW,
                        const float* __restrict__ fW) {
    int i = blockIdx.x * blockDim.x + threadIdx.x;
    if (i < DIM * 256) {
        int k = i >> 8, c = i & 255;
        g_eaWt[i] = (c < DIM) ? eW[c * DIM + k] : aW[(c - DIM) * DIM + k];
    }
    if (i < DIM * DIM) {
        int k = i >> 7, ii = i & 127;
        g_fWat[i] = fW[ii * 256 + k];
        g_fWbt[i] = fW[ii * 256 + 128 + k];
    }
}

// ---------------- w table: softmax(k_emb[c] · Mk^T) over 50 slots ---------
__global__ void k_wtable(const float* __restrict__ k_emb, const float* __restrict__ Mk) {
    __shared__ float mksh[DIM][64];   // [j][m], conflict-free for lane=m
    __shared__ float ksh[4][DIM];
    __shared__ float gmax[4][2], gsum[4][2];
    int tid = threadIdx.x;
    int c0 = blockIdx.x * 16;
    int m = tid & 63, cg = tid >> 6, wh = (tid >> 5) & 1;
    for (int i = tid; i < MM * DIM; i += 256) {
        int mm = i >> 7, j = i & 127;
        mksh[j][mm] = Mk[i];
    }
    for (int cl = 0; cl < 16; cl += 4) {
        int c = c0 + cl + cg;
        __syncthreads();
        for (int j = tid; j < 4 * DIM; j += 256)
            ksh[j >> 7][j & 127] = k_emb[(c0 + cl + (j >> 7)) * DIM + (j & 127)];
        __syncthreads();
        float acc = 0.f;
        if (m < MM) {
            #pragma unroll 8
            for (int j = 0; j < DIM; j++) acc = fmaf(ksh[cg][j], mksh[j][m], acc);
        }
        float lg = (m < MM) ? acc : -1e30f;
        float mx = lg;
        #pragma unroll
        for (int off = 16; off; off >>= 1) mx = fmaxf(mx, __shfl_xor_sync(~0u, mx, off));
        if ((tid & 31) == 0) gmax[cg][wh] = mx;
        __syncthreads();
        mx = fmaxf(gmax[cg][0], gmax[cg][1]);
        float ex = (m < MM) ? __expf(lg - mx) : 0.f;
        float sm = ex;
        #pragma unroll
        for (int off = 16; off; off >>= 1) sm += __shfl_xor_sync(~0u, sm, off);
        if ((tid & 31) == 0) gsum[cg][wh] = sm;
        __syncthreads();
        float s = gsum[cg][0] + gsum[cg][1];
        if (m < MP) g_w[c * MP + m] = ex / s;
    }
}

// ---------------- e/a table: 4000 x 256 GEMM (K=128) + activations -------
__global__ void k_ea(const float* __restrict__ v_emb, const float* __restrict__ e_b,
                     const float* __restrict__ a_b) {
    __shared__ float Xs[32][DIM];
    __shared__ __align__(16) float Ws[16][256];
    int row0 = blockIdx.x * 32;
    int tid = threadIdx.x;
    int tx = tid & 31, ty = tid >> 5;      // col = tx*8, rows = ty*4..ty*4+3
    for (int i = tid; i < 32 * DIM; i += 256) Xs[i >> 7][i & 127] = v_emb[row0 * DIM + i];
    float acc[4][8];
    #pragma unroll
    for (int u = 0; u < 4; u++)
        #pragma unroll
        for (int v = 0; v < 8; v++) acc[u][v] = 0.f;
    for (int kc = 0; kc < DIM; kc += 16) {
        __syncthreads();
        for (int i = tid; i < 16 * 256; i += 256)
            Ws[i >> 8][i & 255] = g_eaWt[(kc + (i >> 8)) * 256 + (i & 255)];
        __syncthreads();
        #pragma unroll
        for (int kk = 0; kk < 16; kk++) {
            float xv[4];
            #pragma unroll
            for (int u = 0; u < 4; u++) xv[u] = Xs[ty * 4 + u][kc + kk];
            float4 w0 = *(const float4*)&Ws[kk][tx * 8];
            float4 w1 = *(const float4*)&Ws[kk][tx * 8 + 4];
            #pragma unroll
            for (int u = 0; u < 4; u++) {
                acc[u][0] = fmaf(xv[u], w0.x, acc[u][0]);
                acc[u][1] = fmaf(xv[u], w0.y, acc[u][1]);
                acc[u][2] = fmaf(xv[u], w0.z, acc[u][2]);
                acc[u][3] = fmaf(xv[u], w0.w, acc[u][3]);
                acc[u][4] = fmaf(xv[u], w1.x, acc[u][4]);
                acc[u][5] = fmaf(xv[u], w1.y, acc[u][5]);
                acc[u][6] = fmaf(xv[u], w1.z, acc[u][6]);
                acc[u][7] = fmaf(xv[u], w1.w, acc[u][7]);
            }
        }
    }
    int col = tx * 8;
    float barr[8];
    #pragma unroll
    for (int v = 0; v < 8; v++) {
        int cc = col + v;
        barr[v] = (cc < DIM) ? e_b[cc] : a_b[cc - DIM];
    }
    #pragma unroll
    for (int u = 0; u < 4; u++) {
        float o[8];
        #pragma unroll
        for (int v = 0; v < 8; v++) {
            float z = acc[u][v] + barr[v];
            o[v] = (col + v < DIM) ? sigmoidf_(z) : tanhf(z);
        }
        int r = row0 + ty * 4 + u;
        *(float4*)&g_ea[r * 256 + col]     = make_float4(o[0], o[1], o[2], o[3]);
        *(float4*)&g_ea[r * 256 + col + 4] = make_float4(o[4], o[5], o[6], o[7]);
    }
}

// ---------------- kf table: 2000 x 128 GEMM (K=128), f_b folded ----------
__global__ void k_kf(const float* __restrict__ k_emb, const float* __restrict__ f_b) {
    __shared__ float Xs[32][DIM];
    __shared__ __align__(16) float Ws[16][DIM];
    int row0 = blockIdx.x * 32;
    int tid = threadIdx.x;
    int tx = tid & 31, ty = tid >> 5;   // col = tx*4, rows = ty*4..
    for (int i = tid; i < 32 * DIM; i += 256) {
        int rr = i >> 7;
        Xs[rr][i & 127] = (row0 + rr < NUM_C) ? k_emb[row0 * DIM + i] : 0.f;
    }
    float acc[4][4];
    #pragma unroll
    for (int u = 0; u < 4; u++)
        #pragma unroll
        for (int v = 0; v < 4; v++) acc[u][v] = 0.f;
    for (int kc = 0; kc < DIM; kc += 16) {
        __syncthreads();
        for (int i = tid; i < 16 * DIM; i += 256)
            Ws[i >> 7][i & 127] = g_fWbt[(kc + (i >> 7)) * DIM + (i & 127)];
        __syncthreads();
        #pragma unroll
        for (int kk = 0; kk < 16; kk++) {
            float xv[4];
            #pragma unroll
            for (int u = 0; u < 4; u++) xv[u] = Xs[ty * 4 + u][kc + kk];
            float4 w0 = *(const float4*)&Ws[kk][tx * 4];
            #pragma unroll
            for (int u = 0; u < 4; u++) {
                acc[u][0] = fmaf(xv[u], w0.x, acc[u][0]);
                acc[u][1] = fmaf(xv[u], w0.y, acc[u][1]);
                acc[u][2] = fmaf(xv[u], w0.z, acc[u][2]);
                acc[u][3] = fmaf(xv[u], w0.w, acc[u][3]);
            }
        }
    }
    int col = tx * 4;
    float b0 = f_b[col], b1 = f_b[col + 1], b2 = f_b[col + 2], b3 = f_b[col + 3];
    #pragma unroll
    for (int u = 0; u < 4; u++) {
        int r = row0 + ty * 4 + u;
        if (r < NUM_C)
            *(float4*)&g_kf[r * DIM + col] =
                make_float4(acc[u][0] + b0, acc[u][1] + b1, acc[u][2] + b2, acc[u][3] + b3);
    }
}

// ---------------- sequential scan: 128 CTAs = 64 batches x 2 d-halves ----
__global__ void k_scan(const int* __restrict__ skill, const int* __restrict__ answer,
                       const float* __restrict__ Mv0) {
    __shared__ int s_sk[TT], s_x[TT];
    __shared__ __align__(16) float w_sh[2][MP];
    __shared__ __align__(16) float e_sh[2][64];
    __shared__ __align__(16) float a_sh[2][64];
    __shared__ __align__(16) float red[8][64];
    int b = blockIdx.x >> 1;
    int dbase = (blockIdx.x & 1) * 64;
    int tid = threadIdx.x;
    int dgi = tid & 31, mg = tid >> 5;
    int d0 = dbase + dgi * 2;

    for (int t = tid; t < TT; t += 256) {
        int s = skill[b * TT + t];
        int aa = answer[b * TT + t];
        if (aa > 1) aa = 1;
        s_sk[t] = s;
        s_x[t] = s + NUM_C * aa;
    }

    float mv[7][2];
    #pragma unroll
    for (int i = 0; i < 7; i++) {
        int m = mg * 7 + i;
        if (m < MM) {
            float2 v = *(const float2*)&Mv0[m * DIM + d0];
            mv[i][0] = v.x; mv[i][1] = v.y;
        } else {
            mv[i][0] = 0.f; mv[i][1] = 0.f;
        }
    }
    __syncthreads();

    // prefetch t = 0 into buffer 0
    if (tid < 184) {
        float pf;
        if (tid < MP)       pf = g_w[s_sk[0] * MP + tid];
        else if (tid < 120) pf = g_ea[s_x[0] * 256 + dbase + (tid - 56)];
        else                pf = g_ea[s_x[0] * 256 + 128 + dbase + (tid - 120)];
        if (tid < MP)       w_sh[0][tid] = pf;
        else if (tid < 120) e_sh[0][tid - 56] = pf;
        else                a_sh[0][tid - 120] = pf;
    }

    for (int t = 0; t < TT; t++) {
        int cur = t & 1, nxt = cur ^ 1;
        __syncthreads();
        // issue prefetch loads for t+1 (consumed after compute; latency hidden)
        float pf = 0.f;
        bool hp = (t + 1 < TT) && (tid < 184);
        if (hp) {
            if (tid < MP)       pf = g_w[s_sk[t + 1] * MP + tid];
            else if (tid < 120) pf = g_ea[s_x[t + 1] * 256 + dbase + (tid - 56)];
            else                pf = g_ea[s_x[t + 1] * 256 + 128 + dbase + (tid - 120)];
        }
        float2 e2 = *(const float2*)&e_sh[cur][dgi * 2];
        float2 a2 = *(const float2*)&a_sh[cur][dgi * 2];
        float acc0 = 0.f, acc1 = 0.f;
        #pragma unroll
        for (int i = 0; i < 7; i++) {
            float wm = w_sh[cur][mg * 7 + i];
            acc0 = fmaf(wm, mv[i][0], acc0);          // read uses PRE-update Mv
            acc1 = fmaf(wm, mv[i][1], acc1);
            mv[i][0] = fmaf(wm, fmaf(-e2.x, mv[i][0], a2.x), mv[i][0]);
            mv[i][1] = fmaf(wm, fmaf(-e2.y, mv[i][1], a2.y), mv[i][1]);
        }
        *(float2*)&red[mg][dgi * 2] = make_float2(acc0, acc1);
        if (hp) {
            if (tid < MP)       w_sh[nxt][tid] = pf;
            else if (tid < 120) e_sh[nxt][tid - 56] = pf;
            else                a_sh[nxt][tid - 120] = pf;
        }
        __syncthreads();
        if (tid < 64) {
            float s = 0.f;
            #pragma unroll
            for (int i = 0; i < 8; i++) s += red[i][tid];
            g_reads[(b * TT + t) * DIM + dbase + tid] = s;
        }
    }
}

// ---------------- f = tanh(reads@fWa + kf[skill]) then gathered pred -----
__global__ void k_fpred(const int* __restrict__ skill, const float* __restrict__ p_W,
                        const float* __restrict__ p_b, float* __restrict__ out) {
    __shared__ float Xs[64][130];                 // reads tile; later reused for f
    __shared__ __align__(16) float Ws[16][DIM];
    __shared__ int s_kf[64], s_nx[64], roff[64];
    int row0 = blockIdx.x * 64;
    int tid = threadIdx.x;
    if (tid < 64) {
        int r = row0 + tid;
        int b = r / 199;
        int t = r - b * 199;
        s_kf[tid] = skill[b * TT + t];
        s_nx[tid] = skill[b * TT + t + 1];
        roff[tid] = (b * TT + t) * DIM;
    }
    __syncthreads();
    for (int i = tid; i < 64 * DIM; i += 256) {
        int rr = i >> 7, k = i & 127;
        Xs[rr][k] = g_reads[roff[rr] + k];
    }
    int tx = tid & 15, ty = tid >> 4;   // col = tx*8, rows = ty*4..
    float acc[4][8];
    #pragma unroll
    for (int u = 0; u < 4; u++)
        #pragma unroll
        for (int v = 0; v < 8; v++) acc[u][v] = 0.f;
    for (int kc = 0; kc < DIM; kc += 16) {
        __syncthreads();
        for (int i = tid; i < 16 * DIM; i += 256)
            Ws[i >> 7][i & 127] = g_fWat[(kc + (i >> 7)) * DIM + (i & 127)];
        __syncthreads();
        #pragma unroll
        for (int kk = 0; kk < 16; kk++) {
            float xv[4];
            #pragma unroll
            for (int u = 0; u < 4; u++) xv[u] = Xs[ty * 4 + u][kc + kk];
            float4 w0 = *(const float4*)&Ws[kk][tx * 8];
            float4 w1 = *(const float4*)&Ws[kk][tx * 8 + 4];
            #pragma unroll
            for (int u = 0; u < 4; u++) {
                acc[u][0] = fmaf(xv[u], w0.x, acc[u][0]);
                acc[u][1] = fmaf(xv[u], w0.y, acc[u][1]);
                acc[u][2] = fmaf(xv[u], w0.z, acc[u][2]);
                acc[u][3] = fmaf(xv[u], w0.w, acc[u][3]);
                acc[u][4] = fmaf(xv[u], w1.x, acc[u][4]);
                acc[u][5] = fmaf(xv[u], w1.y, acc[u][5]);
                acc[u][6] = fmaf(xv[u], w1.z, acc[u][6]);
                acc[u][7] = fmaf(xv[u], w1.w, acc[u][7]);
            }
        }
    }
    __syncthreads();   // everyone done reading Xs -> overwrite with f
    int col = tx * 8;
    #pragma unroll
    for (int u = 0; u < 4; u++) {
        int row = ty * 4 + u;
        int sc = s_kf[row];
        float4 k0 = *(const float4*)&g_kf[sc * DIM + col];
        float4 k1 = *(const float4*)&g_kf[sc * DIM + col + 4];
        Xs[row][col + 0] = tanhf(acc[u][0] + k0.x);
        Xs[row][col + 1] = tanhf(acc[u][1] + k0.y);
        Xs[row][col + 2] = tanhf(acc[u][2] + k0.z);
        Xs[row][col + 3] = tanhf(acc[u][3] + k0.w);
        Xs[row][col + 4] = tanhf(acc[u][4] + k1.x);
        Xs[row][col + 5] = tanhf(acc[u][5] + k1.y);
        Xs[row][col + 6] = tanhf(acc[u][6] + k1.z);
        Xs[row][col + 7] = tanhf(acc[u][7] + k1.w);
    }
    __syncthreads();
    // pred: one warp handles 8 rows; full-warp dot of f(row) with p_W[idx]
    int wid = tid >> 5, lane = tid & 31;
    for (int rr = wid * 8; rr < wid * 8 + 8; rr++) {
        int ns = s_nx[rr];
        int idx = (ns < NUM_C) ? ns : (NUM_C - 1);
        const float* pw = p_W + idx * DIM;
        float a = 0.f;
        #pragma unroll
        for (int q = 0; q < 4; q++) a = fmaf(Xs[rr][lane + 32 * q], pw[lane + 32 * q], a);
        #pragma unroll
        for (int off = 16; off; off >>= 1) a += __shfl_xor_sync(~0u, a, off);
        if (lane == 0) {
            float pr = sigmoidf_(a + p_b[idx]);
            out[row0 + rr] = (ns < NUM_C) ? pr : 0.f;
        }
    }
}

// ---------------- launch ---------------------------------------------------
extern "C" void kernel_launch(void* const* d_in, const int* in_sizes, int n_in,
                              void* d_out, int out_size) {
    const int*   skill  = (const int*)d_in[0];
    const int*   answer = (const int*)d_in[1];
    const float* k_emb  = (const float*)d_in[2];
    const float* v_emb  = (const float*)d_in[3];
    const float* Mk     = (const float*)d_in[4];
    const float* Mv0    = (const float*)d_in[5];
    const float* f_W    = (const float*)d_in[6];
    const float* f_b    = (const float*)d_in[7];
    const float* p_W    = (const float*)d_in[8];
    const float* p_b    = (const float*)d_in[9];
    const float* e_W    = (const float*)d_in[10];
    const float* e_b    = (const float*)d_in[11];
    const float* a_W    = (const float*)d_in[12];
    const float* a_b    = (const float*)d_in[13];
    float* out = (float*)d_out;

    k_setup <<<128, 256>>>(e_W, a_W, f_W);
    k_wtable<<<125, 256>>>(k_emb, Mk);
    k_ea    <<<125, 256>>>(v_emb, e_b, a_b);
    k_kf    <<<63, 256>>>(k_emb, f_b);
    k_scan  <<<128, 256>>>(skill, answer, Mv0);
    k_fpred <<<199, 256>>>(skill, p_W, p_b, out);
}